// round 10
// baseline (speedup 1.0000x reference)
#include <cuda_runtime.h>
#include <stdint.h>

typedef unsigned long long ull;

#define MAX_NODES 100352   // >= 100000, multiple of 16
#define MASK_WORDS (MAX_NODES / 32)       // 3136
#define NCOMP 75           // compact classes: 0 = dead (C6==0), 1..74 alive
#define TAB_BYTES 608      // 75 * 8 rounded to 16
#define EDGE_SMEM (TAB_BYTES + MAX_NODES)   // ~101 KB -> 2 CTAs/SM
#define EDGE_BLOCK 768
#define EDGE_GRID 304      // 2 CTAs x 152 SMs
#define CNT_BLOCK 1024
#define CNT_GRID 304

// packed f32x2 helpers (ptxas never emits these from C++)
#define PACK2(d, lo, hi)  asm("mov.b64 %0, {%1, %2};" : "=l"(d) : "f"(lo), "f"(hi))
#define UNPACK2(lo, hi, s) asm("mov.b64 {%0, %1}, %2;" : "=f"(lo), "=f"(hi) : "l"(s))
#define MUL2(d, a, b)     asm("mul.rn.f32x2 %0, %1, %2;" : "=l"(d) : "l"(a), "l"(b))
#define ADD2(d, a, b)     asm("add.rn.f32x2 %0, %1, %2;" : "=l"(d) : "l"(a), "l"(b))
#define FMA2(d, a, b, c)  asm("fma.rn.f32x2 %0, %1, %2, %3;" : "=l"(d) : "l"(a), "l"(b), "l"(c))

// Scratch (no cudaMalloc allowed)
__device__ int      g_cn[MAX_NODES];
__device__ uint8_t  g_class[MAX_NODES];     // compact class id
__device__ uint32_t g_maskbits[MASK_WORDS]; // bit i = node i is C or N

// Compact class params {R, C6}. 0=dead; 1..5=Z1..5; 6..55=Z8..57; 56..70=Z72..86;
// 71=C_SP2, 72=C_SP3, 73=N_CN2, 74=N_CN3
__constant__ float2 c_cls[NCOMP] = {
    {0.f,0.f},
    {3.6516f,95.99f},{2.1843f,40.67f},{1.2711f,70.21f},{3.3497f,114.51f},
    {2.7079f,152.36f},
    {2.365f,405.57f},{1.5062f,218.45f},{1.8233f,174.81f},{1.3974f,181.7f},
    {3.3515f,263.02f},{3.0102f,228.1f},{3.1629f,359.43f},{3.2554f,3222.12f},
    {2.9539f,2144.49f},{3.0368f,2072.46f},{2.6598f,1357.42f},{4.0877f,1406.65f},
    {4.1275f,1058.36f},{9.7282f,11498.73f},{8.5322f,3361.33f},{7.2344f,2095.91f},
    {5.3605f,1049.31f},{3.718f,966.27f},{3.6408f,1571.36f},{3.4961f,1183.59f},
    {3.5108f,787.76f},{3.0537f,563.93f},{3.0261f,592.91f},{3.1735f,430.82f},
    {3.1773f,812.57f},{3.8357f,4533.53f},{3.1109f,3440.92f},{3.2122f,3859.82f},
    {2.8263f,2729.6f},{2.412f,1864.19f},{1.894f,1175.73f},{11.2061f,32141.18f},
    {6.821f,27655.14f},{7.2367f,2864.2f},{3.901f,3563.45f},{4.0857f,3266.43f},
    {4.045f,3967.23f},{3.4813f,2233.82f},{3.0487f,1393.49f},{2.7795f,1315.09f},
    {2.8673f,1311.47f},{3.3339f,1460.56f},{3.0086f,1662.99f},{3.9919f,8089.97f},
    {3.4209f,6887.05f},{3.5649f,8799.32f},{3.0288f,6136.5f},{2.262f,3757.31f},
    {1.3837f,2561.18f},{12.171f,66580.83f},
    {6.0791f,27593.76f},{5.7661f,15364.65f},{3.6366f,2734.5f},{4.241f,4801.82f},
    {4.1348f,5685.94f},{3.4213f,2786.0f},{3.2486f,2699.79f},{2.9588f,2282.6f},
    {2.9381f,2476.79f},{2.7711f,2988.7f},{2.5816f,2506.63f},{3.785f,8916.84f},
    {3.5381f,8694.22f},{3.6985f,11821.61f},{3.0551f,8410.64f},
    {2.2348f,429.69f},{1.8219f,184.28f},{2.6454f,720.18f},{2.4667f,482.54f}
};

// Z -> compact class id (Z=6/7 handled via cn in node_kernel; dead rows -> 0)
__constant__ uint8_t c_zmap[87] = {
    0, 1,2,3,4,5, 0,0, 6,7,8,9,10,11,12,13,14,15,16,17,18,19,20,21,22,23,24,
    25,26,27,28,29,30,31,32,33,34,35,36,37,38,39,40,41,42,43,44,45,46,47,48,
    49,50,51,52,53,54,55,
    0,0,0,0,0,0,0,0,0,0,0,0,0,0,   // 58..71 dead
    56,57,58,59,60,61,62,63,64,65,66,67,68,69,70
};

// Phase 0: zero output + cn; build bit-packed C/N mask
__global__ void zero_kernel(float* __restrict__ out, const int* __restrict__ Z,
                            int n, int nwords) {
    int i = blockIdx.x * blockDim.x + threadIdx.x;
    if (i < n) {
        out[i] = 0.0f;
        g_cn[i] = 0;
    }
    if (i < nwords) {
        uint32_t w = 0;
        int base = i * 32;
        #pragma unroll 8
        for (int b = 0; b < 32; b++) {
            int idx = base + b;
            if (idx < n) {
                int z = Z[idx];
                if (z == 6 || z == 7) w |= (1u << b);
            }
        }
        g_maskbits[i] = w;
    }
}

// Phase 1: coordination count, only for C/N receivers (bitmask in smem)
__global__ void __launch_bounds__(CNT_BLOCK, 2)
count_kernel(const int* __restrict__ recv, int n4, int n) {
    __shared__ uint32_t s_bits[MASK_WORDS];
    for (int j = threadIdx.x; j < MASK_WORDS; j += blockDim.x)
        s_bits[j] = g_maskbits[j];
    __syncthreads();
    const int4* r4 = (const int4*)recv;
    int stride = gridDim.x * blockDim.x;
    for (int i = blockIdx.x * blockDim.x + threadIdx.x; i < n4; i += stride) {
        int4 t = r4[i];
        if ((s_bits[t.x >> 5] >> (t.x & 31)) & 1u) atomicAdd(&g_cn[t.x], 1);
        if ((s_bits[t.y >> 5] >> (t.y & 31)) & 1u) atomicAdd(&g_cn[t.y], 1);
        if ((s_bits[t.z >> 5] >> (t.z & 31)) & 1u) atomicAdd(&g_cn[t.z], 1);
        if ((s_bits[t.w >> 5] >> (t.w & 31)) & 1u) atomicAdd(&g_cn[t.w], 1);
    }
    if (blockIdx.x == 0 && threadIdx.x == 0) {
        for (int j = n4 * 4; j < n; j++) {
            int t = recv[j];
            if ((s_bits[t >> 5] >> (t & 31)) & 1u) atomicAdd(&g_cn[t], 1);
        }
    }
}

__global__ void count_kernel_scalar(const int* __restrict__ recv, int n) {
    int i = blockIdx.x * blockDim.x + threadIdx.x;
    if (i < n) {
        int t = recv[i];
        if ((g_maskbits[t >> 5] >> (t & 31)) & 1u) atomicAdd(&g_cn[t], 1);
    }
}

// Phase 2: assign compact class id per node
__global__ void node_kernel(const int* __restrict__ Z, int n) {
    int i = blockIdx.x * blockDim.x + threadIdx.x;
    if (i < n) {
        int z = Z[i];
        uint8_t c;
        if (z == 6)      c = (g_cn[i] <= 3) ? 71 : 72;
        else if (z == 7) c = (g_cn[i] <= 2) ? 73 : 74;
        else             c = c_zmap[z];
        g_class[i] = c;
    }
}

// smem: [0, TAB_BYTES) per-class float2 {R^(1/4), sqrt(0.5*C6)}; then class bytes
__device__ __forceinline__ void edge_smem_setup(char* smem) {
    float2* s_par = (float2*)smem;
    if (threadIdx.x < NCOMP) {
        float2 p = c_cls[threadIdx.x];
        s_par[threadIdx.x] = make_float2(sqrtf(sqrtf(p.x)), sqrtf(0.5f * p.y));
    }
    const int4* src = (const int4*)g_class;
    int4* dst = (int4*)(smem + TAB_BYTES);
    for (int j = threadIdx.x; j < MAX_NODES / 16; j += blockDim.x) dst[j] = src[j];
    __syncthreads();
}

// Two edges at once; polynomial chain in packed f32x2.
// e_half = (0.5*C6) * r^14 / ((r^14 + 6*r0^14) * (Rij6 + r^6)) ; out -= e_half*env
__device__ __forceinline__ void edge_pair_sm(const uint8_t* __restrict__ s_cls,
                                             const float2* __restrict__ s_par,
                                             int s0, int t0, float rA,
                                             int s1, int t1, float rB,
                                             float* __restrict__ out) {
    const ull K04  = 0x3ECCCCCD3ECCCCCDULL; //  0.4f
    const ull K4   = 0x4080000040800000ULL; //  4.0f
    const ull K6   = 0x40C0000040C00000ULL; //  6.0f
    const ull K05  = 0x3F0000003F000000ULL; //  0.5f
    const ull Km4  = 0xC0800000C0800000ULL; // -4.0f
    const ull K48  = 0x4240000042400000ULL; //  48f
    const ull Km21 = 0xC1A80000C1A80000ULL; // -21f
    const ull Km28 = 0xC1E00000C1E00000ULL; // -28f
    const ull K1   = 0x3F8000003F800000ULL; //  1.0f

    float2 a0 = s_par[s_cls[s0]], b0 = s_par[s_cls[t0]];
    float2 a1 = s_par[s_cls[s1]], b1 = s_par[s_cls[t1]];
    float p0 = a0.x * b0.x, c0 = a0.y * b0.y;   // Rij^(1/2), sqrt(.5C6s*.5C6r)*? 
    float p1 = a1.x * b1.x, c1 = a1.y * b1.y;   // c = 0.5*sqrt(C6s*C6r) exactly? 
    // note: sqrt(.5C6s)*sqrt(.5C6r) = 0.5*sqrt(C6s*C6r)  -> folds the 0.5 factor

    ull P, C, R;
    PACK2(P, p0, p1); PACK2(C, c0, c1); PACK2(R, rA, rB);

    ull R0;  FMA2(R0, K04, P, K4);          // r0 = 0.4*sqrt(Rij) + 4
    ull R2;  MUL2(R2, R, R);
    ull R4;  MUL2(R4, R2, R2);
    ull R6;  MUL2(R6, R4, R2);
    ull R8;  MUL2(R8, R4, R4);
    ull R14; MUL2(R14, R8, R6);
    ull B2;  MUL2(B2, R0, R0);
    ull B4;  MUL2(B4, B2, B2);
    ull B6;  MUL2(B6, B4, B2);
    ull B8;  MUL2(B8, B4, B4);
    ull B14; MUL2(B14, B8, B6);
    ull P2;  MUL2(P2, P, P);
    ull P4;  MUL2(P4, P2, P2);
    ull P8;  MUL2(P8, P4, P4);
    ull P12; MUL2(P12, P8, P4);             // Rij^6
    ull D1;  FMA2(D1, K6, B14, R14);        // r^14 + 6*r0^14
    ull D2;  ADD2(D2, P12, R6);             // Rij^6 + r^6
    ull DEN; MUL2(DEN, D1, D2);
    ull NUM; MUL2(NUM, C, R14);             // 0.5*C6ij*r^14 (positive)

    // envelope poly: 1 + x^6*(-28 + x*(48 - 21x)), x = 0.5r - 4
    ull X;   FMA2(X, K05, R, Km4);
    ull T;   FMA2(T, Km21, X, K48);
    FMA2(T, T, X, Km28);
    ull X2;  MUL2(X2, X, X);
    ull X4;  MUL2(X4, X2, X2);
    ull X6;  MUL2(X6, X4, X2);
    ull ENV; FMA2(ENV, X6, T, K1);

    float n0, n1, d0, d1, v0, v1;
    UNPACK2(n0, n1, NUM);
    UNPACK2(d0, d1, DEN);
    UNPACK2(v0, v1, ENV);

    v0 = (rA < 8.0f) ? 1.0f : v0;  v0 = (rA < 10.0f) ? v0 : 0.0f;
    v1 = (rB < 8.0f) ? 1.0f : v1;  v1 = (rB < 10.0f) ? v1 : 0.0f;

    float e0 = __fdividef(n0, d0) * v0;
    float e1 = __fdividef(n1, d1) * v1;
    if (e0 != 0.0f) atomicAdd(&out[t0], -e0);
    if (e1 != 0.0f) atomicAdd(&out[t1], -e1);
}

// Phase 3: edge energies, 2 edges/thread/iter, packed math
__global__ void __launch_bounds__(EDGE_BLOCK, 2)
edge_kernel(const int* __restrict__ snd, const int* __restrict__ recv,
            const float* __restrict__ len, float* __restrict__ out,
            int n2, int n) {
    extern __shared__ char smem[];
    edge_smem_setup(smem);
    const float2*  s_par = (const float2*)smem;
    const uint8_t* s_cls = (const uint8_t*)(smem + TAB_BYTES);

    const int2*   s2 = (const int2*)snd;
    const int2*   t2 = (const int2*)recv;
    const float2* r2 = (const float2*)len;
    int stride = gridDim.x * blockDim.x;
    for (int i = blockIdx.x * blockDim.x + threadIdx.x; i < n2; i += stride) {
        int2   s = s2[i];
        int2   t = t2[i];
        float2 r = r2[i];
        edge_pair_sm(s_cls, s_par, s.x, t.x, r.x, s.y, t.y, r.y, out);
    }
    if (blockIdx.x == 0 && threadIdx.x == 0) {
        for (int j = n2 * 2; j < n; j += 1) {
            // scalar tail (pair up with a dummy duplicate, second write predicated off)
            int sj = snd[j], tj = recv[j];
            float rj = len[j];
            float2 a = s_par[s_cls[sj]], b = s_par[s_cls[tj]];
            float p = a.x * b.x, c = a.y * b.y;
            float r0v = fmaf(0.4f, p, 4.0f);
            float rr2 = rj * rj, rr4 = rr2 * rr2, rr6 = rr4 * rr2, rr8 = rr4 * rr4;
            float rr14 = rr8 * rr6;
            float bb2 = r0v * r0v, bb4 = bb2 * bb2, bb8 = bb4 * bb4;
            float bb14 = bb8 * bb4 * bb2;
            float pp2 = p * p, pp4 = pp2 * pp2, pp8 = pp4 * pp4, pp12 = pp8 * pp4;
            float den = fmaf(6.0f, bb14, rr14) * (pp12 + rr6);
            float x = fmaf(0.5f, rj, -4.0f);
            float x2 = x * x, x6 = x2 * x2 * x2;
            float env = 1.0f + x6 * (-28.0f + x * (48.0f - 21.0f * x));
            env = (rj < 8.0f) ? 1.0f : env;
            env = (rj < 10.0f) ? env : 0.0f;
            float e = __fdividef(c * rr14, den) * env;
            if (e != 0.0f) atomicAdd(&out[tj], -e);
        }
    }
}

// Scalar fallback (misaligned edge halves)
__global__ void __launch_bounds__(EDGE_BLOCK, 2)
edge_kernel_scalar(const int* __restrict__ snd, const int* __restrict__ recv,
                   const float* __restrict__ len, float* __restrict__ out, int n) {
    extern __shared__ char smem[];
    edge_smem_setup(smem);
    const float2*  s_par = (const float2*)smem;
    const uint8_t* s_cls = (const uint8_t*)(smem + TAB_BYTES);
    int stride = gridDim.x * blockDim.x;
    for (int i = blockIdx.x * blockDim.x + threadIdx.x; i < n; i += stride) {
        int sj = snd[i], tj = recv[i];
        float rj = len[i];
        float2 a = s_par[s_cls[sj]], b = s_par[s_cls[tj]];
        float p = a.x * b.x, c = a.y * b.y;
        float r0v = fmaf(0.4f, p, 4.0f);
        float rr2 = rj * rj, rr4 = rr2 * rr2, rr6 = rr4 * rr2, rr8 = rr4 * rr4;
        float rr14 = rr8 * rr6;
        float bb2 = r0v * r0v, bb4 = bb2 * bb2, bb8 = bb4 * bb4;
        float bb14 = bb8 * bb4 * bb2;
        float pp2 = p * p, pp4 = pp2 * pp2, pp8 = pp4 * pp4, pp12 = pp8 * pp4;
        float den = fmaf(6.0f, bb14, rr14) * (pp12 + rr6);
        float x = fmaf(0.5f, rj, -4.0f);
        float x2 = x * x, x6 = x2 * x2 * x2;
        float env = 1.0f + x6 * (-28.0f + x * (48.0f - 21.0f * x));
        env = (rj < 8.0f) ? 1.0f : env;
        env = (rj < 10.0f) ? env : 0.0f;
        float e = __fdividef(c * rr14, den) * env;
        if (e != 0.0f) atomicAdd(&out[tj], -e);
    }
}

extern "C" void kernel_launch(void* const* d_in, const int* in_sizes, int n_in,
                              void* d_out, int out_size) {
    const int*   Z   = (const int*)d_in[0];
    const int*   ei  = (const int*)d_in[1];
    const float* len = (const float*)d_in[2];
    float* out = (float*)d_out;

    int n_nodes = in_sizes[0];
    int n_edges = in_sizes[2];
    const int* snd  = ei;
    const int* recv = ei + n_edges;

    static bool attr_done = false;
    if (!attr_done) {
        cudaFuncSetAttribute(edge_kernel,
            cudaFuncAttributeMaxDynamicSharedMemorySize, EDGE_SMEM);
        cudaFuncSetAttribute(edge_kernel_scalar,
            cudaFuncAttributeMaxDynamicSharedMemorySize, EDGE_SMEM);
        attr_done = true;
    }

    const int TB = 256;
    int nwords = (n_nodes + 31) / 32;
    int zthreads = (n_nodes > nwords) ? n_nodes : nwords;
    zero_kernel<<<(zthreads + TB - 1) / TB, TB>>>(out, Z, n_nodes, nwords);

    bool vec_ok = ((n_edges & 3) == 0);
    if (vec_ok) {
        int n4 = n_edges >> 2;
        int n2 = n_edges >> 1;
        count_kernel<<<CNT_GRID, CNT_BLOCK>>>(recv, n4, n_edges);
        node_kernel<<<(n_nodes + TB - 1) / TB, TB>>>(Z, n_nodes);
        edge_kernel<<<EDGE_GRID, EDGE_BLOCK, EDGE_SMEM>>>(snd, recv, len, out, n2, n_edges);
    } else {
        count_kernel_scalar<<<(n_edges + TB - 1) / TB, TB>>>(recv, n_edges);
        node_kernel<<<(n_nodes + TB - 1) / TB, TB>>>(Z, n_nodes);
        edge_kernel_scalar<<<EDGE_GRID, EDGE_BLOCK, EDGE_SMEM>>>(snd, recv, len, out, n_edges);
    }
}

// round 11
// speedup vs baseline: 1.1102x; 1.1102x over previous
#include <cuda_runtime.h>
#include <stdint.h>

#define MAX_NODES 100352   // >= 100000, multiple of 16
#define NCOMP 75           // compact classes: 0 = dead (C6==0), 1..74 alive
#define TAB_BYTES 608      // 75 * 8 rounded to 16
#define EDGE_SMEM (TAB_BYTES + MAX_NODES)   // ~101 KB -> 2 CTAs/SM
#define EDGE_BLOCK 1024
#define EDGE_GRID 304      // 2 CTAs x 152 SMs, one wave
#define CNT_BLOCK 512
#define CNT_GRID 304

// Scratch (no cudaMalloc allowed)
__device__ int     g_cn[MAX_NODES];
__device__ uint8_t g_class[MAX_NODES];  // phase 1: isCN flag; phase 2: compact class id

// Compact class params {R, C6}. 0=dead; 1..5=Z1..5; 6..55=Z8..57; 56..70=Z72..86;
// 71=C_SP2, 72=C_SP3, 73=N_CN2, 74=N_CN3
__constant__ float2 c_cls[NCOMP] = {
    {0.f,0.f},
    {3.6516f,95.99f},{2.1843f,40.67f},{1.2711f,70.21f},{3.3497f,114.51f},
    {2.7079f,152.36f},
    {2.365f,405.57f},{1.5062f,218.45f},{1.8233f,174.81f},{1.3974f,181.7f},
    {3.3515f,263.02f},{3.0102f,228.1f},{3.1629f,359.43f},{3.2554f,3222.12f},
    {2.9539f,2144.49f},{3.0368f,2072.46f},{2.6598f,1357.42f},{4.0877f,1406.65f},
    {4.1275f,1058.36f},{9.7282f,11498.73f},{8.5322f,3361.33f},{7.2344f,2095.91f},
    {5.3605f,1049.31f},{3.718f,966.27f},{3.6408f,1571.36f},{3.4961f,1183.59f},
    {3.5108f,787.76f},{3.0537f,563.93f},{3.0261f,592.91f},{3.1735f,430.82f},
    {3.1773f,812.57f},{3.8357f,4533.53f},{3.1109f,3440.92f},{3.2122f,3859.82f},
    {2.8263f,2729.6f},{2.412f,1864.19f},{1.894f,1175.73f},{11.2061f,32141.18f},
    {6.821f,27655.14f},{7.2367f,2864.2f},{3.901f,3563.45f},{4.0857f,3266.43f},
    {4.045f,3967.23f},{3.4813f,2233.82f},{3.0487f,1393.49f},{2.7795f,1315.09f},
    {2.8673f,1311.47f},{3.3339f,1460.56f},{3.0086f,1662.99f},{3.9919f,8089.97f},
    {3.4209f,6887.05f},{3.5649f,8799.32f},{3.0288f,6136.5f},{2.262f,3757.31f},
    {1.3837f,2561.18f},{12.171f,66580.83f},
    {6.0791f,27593.76f},{5.7661f,15364.65f},{3.6366f,2734.5f},{4.241f,4801.82f},
    {4.1348f,5685.94f},{3.4213f,2786.0f},{3.2486f,2699.79f},{2.9588f,2282.6f},
    {2.9381f,2476.79f},{2.7711f,2988.7f},{2.5816f,2506.63f},{3.785f,8916.84f},
    {3.5381f,8694.22f},{3.6985f,11821.61f},{3.0551f,8410.64f},
    {2.2348f,429.69f},{1.8219f,184.28f},{2.6454f,720.18f},{2.4667f,482.54f}
};

// Z -> compact class id (Z=6/7 handled via cn in node_kernel; dead rows -> 0)
__constant__ uint8_t c_zmap[87] = {
    0, 1,2,3,4,5, 0,0, 6,7,8,9,10,11,12,13,14,15,16,17,18,19,20,21,22,23,24,
    25,26,27,28,29,30,31,32,33,34,35,36,37,38,39,40,41,42,43,44,45,46,47,48,
    49,50,51,52,53,54,55,
    0,0,0,0,0,0,0,0,0,0,0,0,0,0,   // 58..71 dead
    56,57,58,59,60,61,62,63,64,65,66,67,68,69,70
};

// Phase 0: zero output + cn, stash is-C/N flag in g_class (coalesced, 1 elem/thread)
__global__ void zero_kernel(float* __restrict__ out, const int* __restrict__ Z, int n) {
    int i = blockIdx.x * blockDim.x + threadIdx.x;
    if (i < n) {
        out[i] = 0.0f;
        g_cn[i] = 0;
        int z = Z[i];
        g_class[i] = (z == 6 || z == 7) ? 1 : 0;
    }
}

// Phase 1: coordination count, only for C/N receivers (byte mask cached in smem)
__global__ void __launch_bounds__(CNT_BLOCK)
count_kernel(const int* __restrict__ recv, int n4, int n) {
    extern __shared__ uint8_t s_mask[];
    {
        const int4* src = (const int4*)g_class;
        int4* dst = (int4*)s_mask;
        for (int j = threadIdx.x; j < MAX_NODES / 16; j += blockDim.x) dst[j] = src[j];
    }
    __syncthreads();
    const int4* r4 = (const int4*)recv;
    int stride = gridDim.x * blockDim.x;
    for (int i = blockIdx.x * blockDim.x + threadIdx.x; i < n4; i += stride) {
        int4 t = r4[i];
        if (s_mask[t.x]) atomicAdd(&g_cn[t.x], 1);
        if (s_mask[t.y]) atomicAdd(&g_cn[t.y], 1);
        if (s_mask[t.z]) atomicAdd(&g_cn[t.z], 1);
        if (s_mask[t.w]) atomicAdd(&g_cn[t.w], 1);
    }
    if (blockIdx.x == 0 && threadIdx.x == 0) {
        for (int j = n4 * 4; j < n; j++) {
            int t = recv[j];
            if (s_mask[t]) atomicAdd(&g_cn[t], 1);
        }
    }
}

__global__ void count_kernel_scalar(const int* __restrict__ recv, int n) {
    int i = blockIdx.x * blockDim.x + threadIdx.x;
    if (i < n) {
        int t = recv[i];
        if (g_class[t]) atomicAdd(&g_cn[t], 1);
    }
}

// Phase 2: assign compact class id per node
__global__ void node_kernel(const int* __restrict__ Z, int n) {
    int i = blockIdx.x * blockDim.x + threadIdx.x;
    if (i < n) {
        int z = Z[i];
        uint8_t c;
        if (z == 6)      c = (g_cn[i] <= 3) ? 71 : 72;
        else if (z == 7) c = (g_cn[i] <= 2) ? 73 : 74;
        else             c = c_zmap[z];
        g_class[i] = c;
    }
}

// smem: [0, TAB_BYTES) per-class float2 {R^(1/4), sqrt(C6)}; then class bytes
__device__ __forceinline__ void edge_smem_setup(char* smem) {
    float2* s_par = (float2*)smem;
    if (threadIdx.x < NCOMP) {
        float2 p = c_cls[threadIdx.x];
        s_par[threadIdx.x] = make_float2(sqrtf(sqrtf(p.x)), sqrtf(p.y));
    }
    const int4* src = (const int4*)g_class;
    int4* dst = (int4*)(smem + TAB_BYTES);
    for (int j = threadIdx.x; j < MAX_NODES / 16; j += blockDim.x) dst[j] = src[j];
    __syncthreads();
}

__device__ __forceinline__ void edge_one_sm(const uint8_t* __restrict__ s_cls,
                                            const float2* __restrict__ s_par,
                                            int s, int t, float r,
                                            float* __restrict__ out) {
    float2 ps = s_par[s_cls[s]];
    float2 pt = s_par[s_cls[t]];
    float p   = ps.x * pt.x;    // Rij^(1/2)
    float C6  = ps.y * pt.y;    // sqrt(C6_s*C6_r); 0 if either endpoint dead

    float r0 = fmaf(0.4f, p, 4.0f);
    float q  = __fdividef(r0, r);
    float q2 = q * q, q4 = q2 * q2, q8 = q4 * q4;
    float q14 = q8 * q4 * q2;
    float fd = __fdividef(1.0f, fmaf(6.0f, q14, 1.0f));

    float p2 = p * p, p4 = p2 * p2, p8 = p4 * p4;
    float Rij6 = p8 * p4;       // Rij^6

    float r2 = r * r;
    float r6 = r2 * r2 * r2;
    float e = -C6 * __fdividef(fd, Rij6 + r6);

    // envelope via selects (no divergent region)
    float x  = (r - 8.0f) * 0.5f;
    float x2 = x * x, x6 = x2 * x2 * x2;
    float env = 1.0f + x6 * (-28.0f + x * (48.0f - 21.0f * x));
    env = (r < 8.0f)  ? 1.0f : env;
    env = (r < 10.0f) ? env  : 0.0f;
    e *= env;

    if (e != 0.0f) atomicAdd(&out[t], 0.5f * e);
}

// Phase 3: edge energies (vectorized, persistent grid-stride, 64 warps/SM)
__global__ void __launch_bounds__(EDGE_BLOCK, 2)
edge_kernel(const int* __restrict__ snd, const int* __restrict__ recv,
            const float* __restrict__ len, float* __restrict__ out,
            int n4, int n) {
    extern __shared__ char smem[];
    edge_smem_setup(smem);
    const float2*  s_par = (const float2*)smem;
    const uint8_t* s_cls = (const uint8_t*)(smem + TAB_BYTES);

    const int4*   s4 = (const int4*)snd;
    const int4*   t4 = (const int4*)recv;
    const float4* r4 = (const float4*)len;
    int stride = gridDim.x * blockDim.x;
    for (int i = blockIdx.x * blockDim.x + threadIdx.x; i < n4; i += stride) {
        int4   s = s4[i];
        int4   t = t4[i];
        float4 r = r4[i];
        edge_one_sm(s_cls, s_par, s.x, t.x, r.x, out);
        edge_one_sm(s_cls, s_par, s.y, t.y, r.y, out);
        edge_one_sm(s_cls, s_par, s.z, t.z, r.z, out);
        edge_one_sm(s_cls, s_par, s.w, t.w, r.w, out);
    }
    if (blockIdx.x == 0 && threadIdx.x == 0) {
        for (int j = n4 * 4; j < n; j++)
            edge_one_sm(s_cls, s_par, snd[j], recv[j], len[j], out);
    }
}

// Scalar fallback (misaligned edge halves)
__global__ void __launch_bounds__(EDGE_BLOCK, 2)
edge_kernel_scalar(const int* __restrict__ snd, const int* __restrict__ recv,
                   const float* __restrict__ len, float* __restrict__ out, int n) {
    extern __shared__ char smem[];
    edge_smem_setup(smem);
    const float2*  s_par = (const float2*)smem;
    const uint8_t* s_cls = (const uint8_t*)(smem + TAB_BYTES);
    int stride = gridDim.x * blockDim.x;
    for (int i = blockIdx.x * blockDim.x + threadIdx.x; i < n; i += stride)
        edge_one_sm(s_cls, s_par, snd[i], recv[i], len[i], out);
}

extern "C" void kernel_launch(void* const* d_in, const int* in_sizes, int n_in,
                              void* d_out, int out_size) {
    const int*   Z   = (const int*)d_in[0];
    const int*   ei  = (const int*)d_in[1];
    const float* len = (const float*)d_in[2];
    float* out = (float*)d_out;

    int n_nodes = in_sizes[0];
    int n_edges = in_sizes[2];
    const int* snd  = ei;
    const int* recv = ei + n_edges;

    static bool attr_done = false;
    if (!attr_done) {
        cudaFuncSetAttribute(count_kernel,
            cudaFuncAttributeMaxDynamicSharedMemorySize, MAX_NODES);
        cudaFuncSetAttribute(edge_kernel,
            cudaFuncAttributeMaxDynamicSharedMemorySize, EDGE_SMEM);
        cudaFuncSetAttribute(edge_kernel_scalar,
            cudaFuncAttributeMaxDynamicSharedMemorySize, EDGE_SMEM);
        attr_done = true;
    }

    const int TB = 256;
    zero_kernel<<<(n_nodes + TB - 1) / TB, TB>>>(out, Z, n_nodes);

    bool vec_ok = ((n_edges & 3) == 0);
    if (vec_ok) {
        int n4 = n_edges >> 2;
        count_kernel<<<CNT_GRID, CNT_BLOCK, MAX_NODES>>>(recv, n4, n_edges);
        node_kernel<<<(n_nodes + TB - 1) / TB, TB>>>(Z, n_nodes);
        edge_kernel<<<EDGE_GRID, EDGE_BLOCK, EDGE_SMEM>>>(snd, recv, len, out, n4, n_edges);
    } else {
        count_kernel_scalar<<<(n_edges + TB - 1) / TB, TB>>>(recv, n_edges);
        node_kernel<<<(n_nodes + TB - 1) / TB, TB>>>(Z, n_nodes);
        edge_kernel_scalar<<<EDGE_GRID, EDGE_BLOCK, EDGE_SMEM>>>(snd, recv, len, out, n_edges);
    }
}

// round 12
// speedup vs baseline: 1.2032x; 1.0838x over previous
#include <cuda_runtime.h>
#include <stdint.h>

#define MAX_NODES 100352   // >= 100000, multiple of 16
#define MASK_WORDS (MAX_NODES / 32)        // 3136 words = 12.5 KB
#define NCOMP 75           // compact classes: 0 = dead (C6==0), 1..74 alive
#define TAB_BYTES 608      // 75 * 8 rounded to 16
#define EDGE_SMEM (TAB_BYTES + MAX_NODES)  // ~101 KB -> 2 CTAs/SM
#define EDGE_BLOCK 1024
#define EDGE_GRID 304      // 2 CTAs x 152 SMs, one wave
#define CNT_BLOCK 512
#define CNT_GRID 304

// Scratch (no cudaMalloc allowed)
__device__ int      g_cn[MAX_NODES];
__device__ uint8_t  g_class[MAX_NODES];     // compact class id (written in node_kernel)
__device__ uint32_t g_maskbits[MASK_WORDS]; // bit i = node i is C or N

// Compact class params {R, C6}. 0=dead; 1..5=Z1..5; 6..55=Z8..57; 56..70=Z72..86;
// 71=C_SP2, 72=C_SP3, 73=N_CN2, 74=N_CN3
__constant__ float2 c_cls[NCOMP] = {
    {0.f,0.f},
    {3.6516f,95.99f},{2.1843f,40.67f},{1.2711f,70.21f},{3.3497f,114.51f},
    {2.7079f,152.36f},
    {2.365f,405.57f},{1.5062f,218.45f},{1.8233f,174.81f},{1.3974f,181.7f},
    {3.3515f,263.02f},{3.0102f,228.1f},{3.1629f,359.43f},{3.2554f,3222.12f},
    {2.9539f,2144.49f},{3.0368f,2072.46f},{2.6598f,1357.42f},{4.0877f,1406.65f},
    {4.1275f,1058.36f},{9.7282f,11498.73f},{8.5322f,3361.33f},{7.2344f,2095.91f},
    {5.3605f,1049.31f},{3.718f,966.27f},{3.6408f,1571.36f},{3.4961f,1183.59f},
    {3.5108f,787.76f},{3.0537f,563.93f},{3.0261f,592.91f},{3.1735f,430.82f},
    {3.1773f,812.57f},{3.8357f,4533.53f},{3.1109f,3440.92f},{3.2122f,3859.82f},
    {2.8263f,2729.6f},{2.412f,1864.19f},{1.894f,1175.73f},{11.2061f,32141.18f},
    {6.821f,27655.14f},{7.2367f,2864.2f},{3.901f,3563.45f},{4.0857f,3266.43f},
    {4.045f,3967.23f},{3.4813f,2233.82f},{3.0487f,1393.49f},{2.7795f,1315.09f},
    {2.8673f,1311.47f},{3.3339f,1460.56f},{3.0086f,1662.99f},{3.9919f,8089.97f},
    {3.4209f,6887.05f},{3.5649f,8799.32f},{3.0288f,6136.5f},{2.262f,3757.31f},
    {1.3837f,2561.18f},{12.171f,66580.83f},
    {6.0791f,27593.76f},{5.7661f,15364.65f},{3.6366f,2734.5f},{4.241f,4801.82f},
    {4.1348f,5685.94f},{3.4213f,2786.0f},{3.2486f,2699.79f},{2.9588f,2282.6f},
    {2.9381f,2476.79f},{2.7711f,2988.7f},{2.5816f,2506.63f},{3.785f,8916.84f},
    {3.5381f,8694.22f},{3.6985f,11821.61f},{3.0551f,8410.64f},
    {2.2348f,429.69f},{1.8219f,184.28f},{2.6454f,720.18f},{2.4667f,482.54f}
};

// Z -> compact class id (Z=6/7 handled via cn in node_kernel; dead rows -> 0)
__constant__ uint8_t c_zmap[87] = {
    0, 1,2,3,4,5, 0,0, 6,7,8,9,10,11,12,13,14,15,16,17,18,19,20,21,22,23,24,
    25,26,27,28,29,30,31,32,33,34,35,36,37,38,39,40,41,42,43,44,45,46,47,48,
    49,50,51,52,53,54,55,
    0,0,0,0,0,0,0,0,0,0,0,0,0,0,   // 58..71 dead
    56,57,58,59,60,61,62,63,64,65,66,67,68,69,70
};

// Phase 0: zero output + cn; build bit-packed C/N mask via warp ballot
// (grid covers MAX_NODES so every mask word is written)
__global__ void zero_kernel(float* __restrict__ out, const int* __restrict__ Z, int n) {
    int i = blockIdx.x * blockDim.x + threadIdx.x;
    bool cn_flag = false;
    if (i < n) {
        out[i] = 0.0f;
        g_cn[i] = 0;
        int z = Z[i];
        cn_flag = (z == 6 || z == 7);
    }
    uint32_t w = __ballot_sync(0xFFFFFFFFu, cn_flag);
    if ((threadIdx.x & 31) == 0 && (i >> 5) < MASK_WORDS)
        g_maskbits[i >> 5] = w;
}

// Phase 1: coordination count, only for C/N receivers (12.5 KB bitmask in smem)
__global__ void __launch_bounds__(CNT_BLOCK)
count_kernel(const int* __restrict__ recv, int n4, int n) {
    __shared__ uint32_t s_bits[MASK_WORDS];
    for (int j = threadIdx.x; j < MASK_WORDS; j += blockDim.x)
        s_bits[j] = g_maskbits[j];
    __syncthreads();
    const int4* r4 = (const int4*)recv;
    int stride = gridDim.x * blockDim.x;
    for (int i = blockIdx.x * blockDim.x + threadIdx.x; i < n4; i += stride) {
        int4 t = r4[i];
        if ((s_bits[t.x >> 5] >> (t.x & 31)) & 1u) atomicAdd(&g_cn[t.x], 1);
        if ((s_bits[t.y >> 5] >> (t.y & 31)) & 1u) atomicAdd(&g_cn[t.y], 1);
        if ((s_bits[t.z >> 5] >> (t.z & 31)) & 1u) atomicAdd(&g_cn[t.z], 1);
        if ((s_bits[t.w >> 5] >> (t.w & 31)) & 1u) atomicAdd(&g_cn[t.w], 1);
    }
    if (blockIdx.x == 0 && threadIdx.x == 0) {
        for (int j = n4 * 4; j < n; j++) {
            int t = recv[j];
            if ((s_bits[t >> 5] >> (t & 31)) & 1u) atomicAdd(&g_cn[t], 1);
        }
    }
}

__global__ void count_kernel_scalar(const int* __restrict__ recv, int n) {
    int i = blockIdx.x * blockDim.x + threadIdx.x;
    if (i < n) {
        int t = recv[i];
        if ((g_maskbits[t >> 5] >> (t & 31)) & 1u) atomicAdd(&g_cn[t], 1);
    }
}

// Phase 2: assign compact class id per node
__global__ void node_kernel(const int* __restrict__ Z, int n) {
    int i = blockIdx.x * blockDim.x + threadIdx.x;
    if (i < n) {
        int z = Z[i];
        uint8_t c;
        if (z == 6)      c = (g_cn[i] <= 3) ? 71 : 72;
        else if (z == 7) c = (g_cn[i] <= 2) ? 73 : 74;
        else             c = c_zmap[z];
        g_class[i] = c;
    }
}

// smem: [0, TAB_BYTES) per-class float2 {R^(1/4), sqrt(C6)}; then class bytes
__device__ __forceinline__ void edge_smem_setup(char* smem) {
    float2* s_par = (float2*)smem;
    if (threadIdx.x < NCOMP) {
        float2 p = c_cls[threadIdx.x];
        s_par[threadIdx.x] = make_float2(sqrtf(sqrtf(p.x)), sqrtf(p.y));
    }
    const int4* src = (const int4*)g_class;
    int4* dst = (int4*)(smem + TAB_BYTES);
    for (int j = threadIdx.x; j < MAX_NODES / 16; j += blockDim.x) dst[j] = src[j];
    __syncthreads();
}

__device__ __forceinline__ void edge_one_sm(const uint8_t* __restrict__ s_cls,
                                            const float2* __restrict__ s_par,
                                            int s, int t, float r,
                                            float* __restrict__ out) {
    float2 ps = s_par[s_cls[s]];
    float2 pt = s_par[s_cls[t]];
    float p   = ps.x * pt.x;    // Rij^(1/2)
    float C6  = ps.y * pt.y;    // sqrt(C6_s*C6_r); 0 if either endpoint dead

    float r0 = fmaf(0.4f, p, 4.0f);
    float q  = __fdividef(r0, r);
    float q2 = q * q, q4 = q2 * q2, q8 = q4 * q4;
    float q14 = q8 * q4 * q2;
    float fd = __fdividef(1.0f, fmaf(6.0f, q14, 1.0f));

    float p2 = p * p, p4 = p2 * p2, p8 = p4 * p4;
    float Rij6 = p8 * p4;       // Rij^6

    float r2 = r * r;
    float r6 = r2 * r2 * r2;
    float e = -C6 * __fdividef(fd, Rij6 + r6);

    // envelope via selects (no divergent region)
    float x  = (r - 8.0f) * 0.5f;
    float x2 = x * x, x6 = x2 * x2 * x2;
    float env = 1.0f + x6 * (-28.0f + x * (48.0f - 21.0f * x));
    env = (r < 8.0f)  ? 1.0f : env;
    env = (r < 10.0f) ? env  : 0.0f;
    e *= env;

    if (e != 0.0f) atomicAdd(&out[t], 0.5f * e);
}

// Phase 3: edge energies (vectorized, persistent grid-stride, 64 warps/SM)
__global__ void __launch_bounds__(EDGE_BLOCK, 2)
edge_kernel(const int* __restrict__ snd, const int* __restrict__ recv,
            const float* __restrict__ len, float* __restrict__ out,
            int n4, int n) {
    extern __shared__ char smem[];
    edge_smem_setup(smem);
    const float2*  s_par = (const float2*)smem;
    const uint8_t* s_cls = (const uint8_t*)(smem + TAB_BYTES);

    const int4*   s4 = (const int4*)snd;
    const int4*   t4 = (const int4*)recv;
    const float4* r4 = (const float4*)len;
    int stride = gridDim.x * blockDim.x;
    for (int i = blockIdx.x * blockDim.x + threadIdx.x; i < n4; i += stride) {
        int4   s = s4[i];
        int4   t = t4[i];
        float4 r = r4[i];
        edge_one_sm(s_cls, s_par, s.x, t.x, r.x, out);
        edge_one_sm(s_cls, s_par, s.y, t.y, r.y, out);
        edge_one_sm(s_cls, s_par, s.z, t.z, r.z, out);
        edge_one_sm(s_cls, s_par, s.w, t.w, r.w, out);
    }
    if (blockIdx.x == 0 && threadIdx.x == 0) {
        for (int j = n4 * 4; j < n; j++)
            edge_one_sm(s_cls, s_par, snd[j], recv[j], len[j], out);
    }
}

// Scalar fallback (misaligned edge halves)
__global__ void __launch_bounds__(EDGE_BLOCK, 2)
edge_kernel_scalar(const int* __restrict__ snd, const int* __restrict__ recv,
                   const float* __restrict__ len, float* __restrict__ out, int n) {
    extern __shared__ char smem[];
    edge_smem_setup(smem);
    const float2*  s_par = (const float2*)smem;
    const uint8_t* s_cls = (const uint8_t*)(smem + TAB_BYTES);
    int stride = gridDim.x * blockDim.x;
    for (int i = blockIdx.x * blockDim.x + threadIdx.x; i < n; i += stride)
        edge_one_sm(s_cls, s_par, snd[i], recv[i], len[i], out);
}

extern "C" void kernel_launch(void* const* d_in, const int* in_sizes, int n_in,
                              void* d_out, int out_size) {
    const int*   Z   = (const int*)d_in[0];
    const int*   ei  = (const int*)d_in[1];
    const float* len = (const float*)d_in[2];
    float* out = (float*)d_out;

    int n_nodes = in_sizes[0];
    int n_edges = in_sizes[2];
    const int* snd  = ei;
    const int* recv = ei + n_edges;

    static bool attr_done = false;
    if (!attr_done) {
        cudaFuncSetAttribute(edge_kernel,
            cudaFuncAttributeMaxDynamicSharedMemorySize, EDGE_SMEM);
        cudaFuncSetAttribute(edge_kernel_scalar,
            cudaFuncAttributeMaxDynamicSharedMemorySize, EDGE_SMEM);
        attr_done = true;
    }

    const int TB = 256;
    // Cover MAX_NODES so every g_maskbits word gets written (nodes >= n -> 0 bits)
    zero_kernel<<<(MAX_NODES + TB - 1) / TB, TB>>>(out, Z, n_nodes);

    bool vec_ok = ((n_edges & 3) == 0);
    if (vec_ok) {
        int n4 = n_edges >> 2;
        count_kernel<<<CNT_GRID, CNT_BLOCK>>>(recv, n4, n_edges);
        node_kernel<<<(n_nodes + TB - 1) / TB, TB>>>(Z, n_nodes);
        edge_kernel<<<EDGE_GRID, EDGE_BLOCK, EDGE_SMEM>>>(snd, recv, len, out, n4, n_edges);
    } else {
        count_kernel_scalar<<<(n_edges + TB - 1) / TB, TB>>>(recv, n_edges);
        node_kernel<<<(n_nodes + TB - 1) / TB, TB>>>(Z, n_nodes);
        edge_kernel_scalar<<<EDGE_GRID, EDGE_BLOCK, EDGE_SMEM>>>(snd, recv, len, out, n_edges);
    }
}